// round 3
// baseline (speedup 1.0000x reference)
#include <cuda_runtime.h>

#define Nn 50000
#define Rr 16
#define Hh 32
#define Ll 8
#define Ee 1600000

// Scratch (static __device__ arrays: allocation-free per harness rules)
__device__ __align__(16) int   g_cnt[Rr * Nn];      // per-(relation,dst) edge counts
__device__ __align__(16) float g_h1[Nn * Hh];       // layer-1 hidden (agg -> relu'd)
__device__ __align__(16) float g_W2t[Rr * Ll * Hh]; // W2 transposed to [r][l][h]

// ---------------------------------------------------------------------------
// Zero all accumulators (d_out is poisoned to 0xAA by the harness)
// ---------------------------------------------------------------------------
__global__ void k_zero(float* __restrict__ out) {
    int i = blockIdx.x * blockDim.x + threadIdx.x;
    int stride = gridDim.x * blockDim.x;
    for (int j = i; j < Rr * Nn; j += stride) g_cnt[j] = 0;
    for (int j = i; j < Nn * Hh; j += stride) g_h1[j] = 0.0f;
    for (int j = i; j < Nn * Ll; j += stride) out[j] = 0.0f;
}

// ---------------------------------------------------------------------------
// Transpose W2 [r][h][l] -> [r][l][h] so layer-2 threads get contiguous f4 loads
// ---------------------------------------------------------------------------
__global__ void k_w2t(const float* __restrict__ W2) {
    int i = blockIdx.x * blockDim.x + threadIdx.x;
    if (i < Rr * Hh * Ll) {
        int r = i / (Hh * Ll);
        int rem = i - r * (Hh * Ll);
        int h = rem / Ll;
        int l = rem - h * Ll;
        g_W2t[(r * Ll + l) * Hh + h] = W2[i];
    }
}

// ---------------------------------------------------------------------------
// Per-(relation,dst) edge counts: seg = r*N + dst
// ---------------------------------------------------------------------------
__global__ void k_count(const int* __restrict__ et, const int* __restrict__ dst) {
    int e = blockIdx.x * blockDim.x + threadIdx.x;
    if (e < Ee) {
        atomicAdd(&g_cnt[et[e] * Nn + dst[e]], 1);
    }
}

// ---------------------------------------------------------------------------
// Layer 1: warp per edge.  lane = h.
//   g_h1[dst, h] += W1[r, src, h] * (1/max(cnt[r*N+dst],1))
// W1 row is one aligned 128B line -> single coalesced LDG.32 across the warp.
// ---------------------------------------------------------------------------
__global__ void k_layer1(const int* __restrict__ src, const int* __restrict__ dst,
                         const int* __restrict__ et, const float* __restrict__ W1) {
    int t = blockIdx.x * blockDim.x + threadIdx.x;
    int e = t >> 5;
    int lane = t & 31;
    if (e >= Ee) return;
    int s = __ldg(src + e);
    int d = __ldg(dst + e);
    int r = __ldg(et + e);
    float c = (float)g_cnt[r * Nn + d];
    float norm = 1.0f / fmaxf(c, 1.0f);
    float w = __ldg(W1 + ((r * Nn + s) * Hh + lane));
    atomicAdd(&g_h1[d * Hh + lane], w * norm);
}

// ---------------------------------------------------------------------------
// h1 = relu(agg1 + root1 + b1)
// ---------------------------------------------------------------------------
__global__ void k_relu(const float* __restrict__ root1, const float* __restrict__ b1) {
    int i = blockIdx.x * blockDim.x + threadIdx.x;
    if (i < Nn * Hh) {
        float v = g_h1[i] + root1[i] + b1[i & (Hh - 1)];
        g_h1[i] = v > 0.0f ? v : 0.0f;
    }
}

// ---------------------------------------------------------------------------
// Layer 2 edge pass: 8 threads per edge, thread l computes
//   y_l = sum_h h1[src,h] * W2[r,h,l]     (via transposed W2t[r][l][h])
//   out[dst,l] += norm * y_l
// h1 row: 8 lanes of the group load the SAME float4 -> L1 broadcast.
// W2t column: contiguous 32 floats -> 8x LDG.128, 16KB L1-resident.
// ---------------------------------------------------------------------------
__global__ void k_layer2(const int* __restrict__ src, const int* __restrict__ dst,
                         const int* __restrict__ et, float* __restrict__ out) {
    int t = blockIdx.x * blockDim.x + threadIdx.x;
    int e = t >> 3;
    int l = t & 7;
    if (e >= Ee) return;
    int s = __ldg(src + e);
    int d = __ldg(dst + e);
    int r = __ldg(et + e);
    float c = (float)g_cnt[r * Nn + d];
    float norm = 1.0f / fmaxf(c, 1.0f);

    const float4* hp = (const float4*)(g_h1 + s * Hh);
    const float4* wp = (const float4*)(g_W2t + (r * Ll + l) * Hh);

    float y = 0.0f;
#pragma unroll
    for (int j = 0; j < 8; j++) {
        float4 hv = hp[j];
        float4 wv = wp[j];
        y += hv.x * wv.x + hv.y * wv.y + hv.z * wv.z + hv.w * wv.w;
    }
    atomicAdd(&out[d * Ll + l], norm * y);
}

// ---------------------------------------------------------------------------
// Final: out[n,l] = sigmoid(edge_acc[n,l] + (h1[n,:] @ root2)[l] + b2[l])
// ---------------------------------------------------------------------------
__global__ void k_final(const float* __restrict__ root2, const float* __restrict__ b2,
                        float* __restrict__ out) {
    __shared__ float sR[Hh * Ll];
    __shared__ float sB[Ll];
    for (int i = threadIdx.x; i < Hh * Ll; i += blockDim.x) sR[i] = root2[i];
    if (threadIdx.x < Ll) sB[threadIdx.x] = b2[threadIdx.x];
    __syncthreads();

    int n = blockIdx.x * blockDim.x + threadIdx.x;
    if (n >= Nn) return;

    float y[Ll];
#pragma unroll
    for (int l = 0; l < Ll; l++) y[l] = sB[l];

    const float4* hp = (const float4*)(g_h1 + n * Hh);
#pragma unroll
    for (int j = 0; j < 8; j++) {
        float4 hv = hp[j];
        float hvals[4] = {hv.x, hv.y, hv.z, hv.w};
#pragma unroll
        for (int k = 0; k < 4; k++) {
            int h = j * 4 + k;
#pragma unroll
            for (int l = 0; l < Ll; l++) y[l] += hvals[k] * sR[h * Ll + l];
        }
    }

#pragma unroll
    for (int l = 0; l < Ll; l++) {
        float v = out[n * Ll + l] + y[l];
        out[n * Ll + l] = 1.0f / (1.0f + expf(-v));
    }
}

// ---------------------------------------------------------------------------
extern "C" void kernel_launch(void* const* d_in, const int* in_sizes, int n_in,
                              void* d_out, int out_size) {
    const int* ei    = (const int*)d_in[0];    // edge_index [2, E]
    const int* et    = (const int*)d_in[1];    // edge_type  [E]
    const float* W1  = (const float*)d_in[2];  // [R, N, H]
    const float* rt1 = (const float*)d_in[3];  // [N, H]
    const float* b1  = (const float*)d_in[4];  // [H]
    const float* W2  = (const float*)d_in[5];  // [R, H, L]
    const float* rt2 = (const float*)d_in[6];  // [H, L]
    const float* b2  = (const float*)d_in[7];  // [L]
    float* out = (float*)d_out;                // [N, L]

    const int* src = ei;
    const int* dst = ei + Ee;

    k_zero<<<2048, 256>>>(out);
    k_w2t<<<(Rr * Hh * Ll + 255) / 256, 256>>>(W2);
    k_count<<<(Ee + 255) / 256, 256>>>(et, dst);
    k_layer1<<<Ee / 8, 256>>>(src, dst, et, W1);   // 32 threads/edge
    k_relu<<<(Nn * Hh + 255) / 256, 256>>>(rt1, b1);
    k_layer2<<<Ee / 32, 256>>>(src, dst, et, out); // 8 threads/edge
    k_final<<<(Nn + 255) / 256, 256>>>(rt2, b2, out);
}

// round 4
// speedup vs baseline: 4.9899x; 4.9899x over previous
#include <cuda_runtime.h>

#define Nn 50000
#define Rr 16
#define Hh 32
#define Ll 8
#define Ee 1600000

// Scratch (static __device__ arrays: allocation-free per harness rules)
__device__ __align__(16) int   g_cnt[Rr * Nn];       // per-(relation,dst) edge counts
__device__ __align__(16) float g_norm[Rr * Nn];      // 1/max(cnt,1)
__device__ __align__(16) float g_h1[Nn * Hh];        // layer-1 hidden (agg -> relu'd)
__device__ __align__(16) float g_T[Rr * Nn * Ll];    // T[r,n,l] = (h1[n,:] @ W2[r])[l]

// Vector reduction: 4x fp32 add in one L2 atomic op (sm_90+)
__device__ __forceinline__ void red_add_v4(float* p, float4 v) {
    asm volatile("red.global.add.v4.f32 [%0], {%1,%2,%3,%4};"
                 :: "l"(p), "f"(v.x), "f"(v.y), "f"(v.z), "f"(v.w)
                 : "memory");
}

// ---------------------------------------------------------------------------
// Zero accumulators (d_out is poisoned to 0xAA by the harness)
// ---------------------------------------------------------------------------
__global__ void k_zero(float* __restrict__ out) {
    int i = blockIdx.x * blockDim.x + threadIdx.x;
    int stride = gridDim.x * blockDim.x;
    for (int j = i; j < Rr * Nn; j += stride) g_cnt[j] = 0;
    for (int j = i; j < Nn * Hh; j += stride) g_h1[j] = 0.0f;
    for (int j = i; j < Nn * Ll; j += stride) out[j] = 0.0f;
}

// ---------------------------------------------------------------------------
// Per-(relation,dst) edge counts. 4 edges per thread via int4 index loads.
// ---------------------------------------------------------------------------
__global__ void k_count(const int* __restrict__ et, const int* __restrict__ dst) {
    int g = blockIdx.x * blockDim.x + threadIdx.x;
    if (g >= Ee / 4) return;
    int e0 = g * 4;
    int4 d4 = *(const int4*)(dst + e0);
    int4 r4 = *(const int4*)(et + e0);
    atomicAdd(&g_cnt[r4.x * Nn + d4.x], 1);
    atomicAdd(&g_cnt[r4.y * Nn + d4.y], 1);
    atomicAdd(&g_cnt[r4.z * Nn + d4.z], 1);
    atomicAdd(&g_cnt[r4.w * Nn + d4.w], 1);
}

// ---------------------------------------------------------------------------
// norm[r,d] = 1/max(cnt,1)
// ---------------------------------------------------------------------------
__global__ void k_norm() {
    int i = blockIdx.x * blockDim.x + threadIdx.x;
    if (i < Rr * Nn) g_norm[i] = 1.0f / fmaxf((float)g_cnt[i], 1.0f);
}

// ---------------------------------------------------------------------------
// Layer 1: 8 threads per edge (quarter-row each), 4 edges per thread.
//   g_h1[dst, q*4..q*4+3] += W1[r, src, q*4..] * norm[r,dst]
// int4 index loads (broadcast across the 8-lane group), 4 independent
// LDG.128 W1 loads (MLP=4), 4 vector REDs.
// ---------------------------------------------------------------------------
__global__ void k_layer1(const int* __restrict__ src, const int* __restrict__ dst,
                         const int* __restrict__ et, const float* __restrict__ W1) {
    int g = blockIdx.x * blockDim.x + threadIdx.x;
    int grp = g >> 3;        // which edge-quad
    int q = g & 7;           // which quarter of the 32-wide row
    if (grp >= Ee / 4) return;
    int e0 = grp * 4;

    int4 s4 = *(const int4*)(src + e0);
    int4 d4 = *(const int4*)(dst + e0);
    int4 r4 = *(const int4*)(et + e0);
    int ss[4] = {s4.x, s4.y, s4.z, s4.w};
    int dd[4] = {d4.x, d4.y, d4.z, d4.w};
    int rr[4] = {r4.x, r4.y, r4.z, r4.w};

    float  nn[4];
    float4 ww[4];
#pragma unroll
    for (int k = 0; k < 4; k++) {
        nn[k] = g_norm[rr[k] * Nn + dd[k]];
        ww[k] = *(const float4*)(W1 + (rr[k] * Nn + ss[k]) * Hh + q * 4);
    }
#pragma unroll
    for (int k = 0; k < 4; k++) {
        float4 v = make_float4(ww[k].x * nn[k], ww[k].y * nn[k],
                               ww[k].z * nn[k], ww[k].w * nn[k]);
        red_add_v4(&g_h1[dd[k] * Hh + q * 4], v);
    }
}

// ---------------------------------------------------------------------------
// h1 = relu(agg1 + root1 + b1)
// ---------------------------------------------------------------------------
__global__ void k_relu(const float* __restrict__ root1, const float* __restrict__ b1) {
    int i = blockIdx.x * blockDim.x + threadIdx.x;
    if (i < Nn * Hh) {
        float v = g_h1[i] + root1[i] + b1[i & (Hh - 1)];
        g_h1[i] = v > 0.0f ? v : 0.0f;
    }
}

// ---------------------------------------------------------------------------
// T[r,n,l] = sum_h h1[n,h] * W2[r,h,l].   Block = 256 threads = 32 nodes x 8 l.
// W2 (16KB) staged in shared; LDS reads are 8-consecutive-floats with 4-way
// broadcast -> conflict-free. Writes coalesce per r (4 nodes x 8 l = 128B).
// ---------------------------------------------------------------------------
__global__ void k_T(const float* __restrict__ W2) {
    __shared__ float sW[Rr * Hh * Ll];   // [r][h][l], 16KB
    for (int i = threadIdx.x; i < Rr * Hh * Ll; i += blockDim.x) sW[i] = W2[i];
    __syncthreads();

    int n = blockIdx.x * 32 + (threadIdx.x >> 3);
    int l = threadIdx.x & 7;
    if (n >= Nn) return;

    float acc[Rr];
#pragma unroll
    for (int r = 0; r < Rr; r++) acc[r] = 0.0f;

    const float4* hp = (const float4*)(g_h1 + n * Hh);
#pragma unroll
    for (int j = 0; j < 8; j++) {
        float4 hv = hp[j];
        float hs[4] = {hv.x, hv.y, hv.z, hv.w};
#pragma unroll
        for (int k = 0; k < 4; k++) {
            int h = j * 4 + k;
#pragma unroll
            for (int r = 0; r < Rr; r++)
                acc[r] += hs[k] * sW[(r * Hh + h) * Ll + l];
        }
    }
#pragma unroll
    for (int r = 0; r < Rr; r++) g_T[(r * Nn + n) * Ll + l] = acc[r];
}

// ---------------------------------------------------------------------------
// Layer 2 edge pass: 2 threads per edge (half-row each), 4 edges per thread.
//   out[dst, half*4..] += norm[r,dst] * T[r, src, half*4..]
// T is 25.6MB -> L2-resident gathers.
// ---------------------------------------------------------------------------
__global__ void k_layer2(const int* __restrict__ src, const int* __restrict__ dst,
                         const int* __restrict__ et, float* __restrict__ out) {
    int g = blockIdx.x * blockDim.x + threadIdx.x;
    int grp = g >> 1;
    int half = g & 1;
    if (grp >= Ee / 4) return;
    int e0 = grp * 4;

    int4 s4 = *(const int4*)(src + e0);
    int4 d4 = *(const int4*)(dst + e0);
    int4 r4 = *(const int4*)(et + e0);
    int ss[4] = {s4.x, s4.y, s4.z, s4.w};
    int dd[4] = {d4.x, d4.y, d4.z, d4.w};
    int rr[4] = {r4.x, r4.y, r4.z, r4.w};

    float  nn[4];
    float4 tv[4];
#pragma unroll
    for (int k = 0; k < 4; k++) {
        nn[k] = g_norm[rr[k] * Nn + dd[k]];
        tv[k] = *(const float4*)(g_T + (rr[k] * Nn + ss[k]) * Ll + half * 4);
    }
#pragma unroll
    for (int k = 0; k < 4; k++) {
        float4 v = make_float4(tv[k].x * nn[k], tv[k].y * nn[k],
                               tv[k].z * nn[k], tv[k].w * nn[k]);
        red_add_v4(&out[dd[k] * Ll + half * 4], v);
    }
}

// ---------------------------------------------------------------------------
// Final: out[n,l] = sigmoid(edge_acc[n,l] + (h1[n,:] @ root2)[l] + b2[l])
// ---------------------------------------------------------------------------
__global__ void k_final(const float* __restrict__ root2, const float* __restrict__ b2,
                        float* __restrict__ out) {
    __shared__ float sR[Hh * Ll];
    __shared__ float sB[Ll];
    for (int i = threadIdx.x; i < Hh * Ll; i += blockDim.x) sR[i] = root2[i];
    if (threadIdx.x < Ll) sB[threadIdx.x] = b2[threadIdx.x];
    __syncthreads();

    int n = blockIdx.x * blockDim.x + threadIdx.x;
    if (n >= Nn) return;

    float y[Ll];
#pragma unroll
    for (int l = 0; l < Ll; l++) y[l] = sB[l];

    const float4* hp = (const float4*)(g_h1 + n * Hh);
#pragma unroll
    for (int j = 0; j < 8; j++) {
        float4 hv = hp[j];
        float hvals[4] = {hv.x, hv.y, hv.z, hv.w};
#pragma unroll
        for (int k = 0; k < 4; k++) {
            int h = j * 4 + k;
#pragma unroll
            for (int l = 0; l < Ll; l++) y[l] += hvals[k] * sR[h * Ll + l];
        }
    }

#pragma unroll
    for (int l = 0; l < Ll; l++) {
        float v = out[n * Ll + l] + y[l];
        out[n * Ll + l] = 1.0f / (1.0f + expf(-v));
    }
}

// ---------------------------------------------------------------------------
extern "C" void kernel_launch(void* const* d_in, const int* in_sizes, int n_in,
                              void* d_out, int out_size) {
    const int* ei    = (const int*)d_in[0];    // edge_index [2, E]
    const int* et    = (const int*)d_in[1];    // edge_type  [E]
    const float* W1  = (const float*)d_in[2];  // [R, N, H]
    const float* rt1 = (const float*)d_in[3];  // [N, H]
    const float* b1  = (const float*)d_in[4];  // [H]
    const float* W2  = (const float*)d_in[5];  // [R, H, L]
    const float* rt2 = (const float*)d_in[6];  // [H, L]
    const float* b2  = (const float*)d_in[7];  // [L]
    float* out = (float*)d_out;                // [N, L]

    const int* src = ei;
    const int* dst = ei + Ee;

    k_zero<<<1024, 256>>>(out);
    k_count<<<(Ee / 4 + 255) / 256, 256>>>(et, dst);
    k_norm<<<(Rr * Nn + 255) / 256, 256>>>();
    k_layer1<<<(Ee / 4) * 8 / 256, 256>>>(src, dst, et, W1);   // 8 thr/edge, 4 edges/thr
    k_relu<<<(Nn * Hh + 255) / 256, 256>>>(rt1, b1);
    k_T<<<(Nn + 31) / 32, 256>>>(W2);
    k_layer2<<<(Ee / 4) * 2 / 256, 256>>>(src, dst, et, out);  // 2 thr/edge, 4 edges/thr
    k_final<<<(Nn + 255) / 256, 256>>>(rt2, b2, out);
}

// round 5
// speedup vs baseline: 5.0121x; 1.0045x over previous
#include <cuda_runtime.h>

#define Nn 50000
#define Rr 16
#define Hh 32
#define Ll 8
#define Ee 1600000

// Scratch (static __device__ arrays: allocation-free per harness rules)
__device__ __align__(16) int   g_cnt[Rr * Nn];       // per-(relation,dst) edge counts
__device__ __align__(16) float g_norm[Rr * Nn];      // 1/max(cnt,1)
__device__ __align__(16) float g_h1[Nn * Hh];        // layer-1 hidden (agg -> relu'd)
__device__ __align__(16) float g_T[Rr * Nn * Ll];    // T[r,n,l] = (h1[n,:] @ W2[r])[l]

// Vector reduction: 4x fp32 add in one L2 atomic op (sm_90+)
__device__ __forceinline__ void red_add_v4(float* p, float4 v) {
    asm volatile("red.global.add.v4.f32 [%0], {%1,%2,%3,%4};"
                 :: "l"(p), "f"(v.x), "f"(v.y), "f"(v.z), "f"(v.w)
                 : "memory");
}

// ---------------------------------------------------------------------------
// Zero accumulators (d_out is poisoned to 0xAA by the harness)
// ---------------------------------------------------------------------------
__global__ void k_zero(float* __restrict__ out) {
    int i = blockIdx.x * blockDim.x + threadIdx.x;
    int stride = gridDim.x * blockDim.x;
    for (int j = i; j < Rr * Nn; j += stride) g_cnt[j] = 0;
    for (int j = i; j < Nn * Hh; j += stride) g_h1[j] = 0.0f;
    for (int j = i; j < Nn * Ll; j += stride) out[j] = 0.0f;
}

// ---------------------------------------------------------------------------
// Per-(relation,dst) edge counts. 4 edges per thread via int4 index loads.
// ---------------------------------------------------------------------------
__global__ void k_count(const int* __restrict__ et, const int* __restrict__ dst) {
    int g = blockIdx.x * blockDim.x + threadIdx.x;
    if (g >= Ee / 4) return;
    int e0 = g * 4;
    int4 d4 = *(const int4*)(dst + e0);
    int4 r4 = *(const int4*)(et + e0);
    atomicAdd(&g_cnt[r4.x * Nn + d4.x], 1);
    atomicAdd(&g_cnt[r4.y * Nn + d4.y], 1);
    atomicAdd(&g_cnt[r4.z * Nn + d4.z], 1);
    atomicAdd(&g_cnt[r4.w * Nn + d4.w], 1);
}

// ---------------------------------------------------------------------------
// norm[r,d] = 1/max(cnt,1)
// ---------------------------------------------------------------------------
__global__ void k_norm() {
    int i = blockIdx.x * blockDim.x + threadIdx.x;
    if (i < Rr * Nn) g_norm[i] = 1.0f / fmaxf((float)g_cnt[i], 1.0f);
}

// ---------------------------------------------------------------------------
// Layer 1: 8 threads per edge (quarter-row each), 4 edges per thread.
//   g_h1[dst, q*4..q*4+3] += W1[r, src, q*4..] * norm[r,dst]
// int4 index loads (broadcast across the 8-lane group), 4 independent
// LDG.128 W1 loads (MLP=4), 4 vector REDs.
// ---------------------------------------------------------------------------
__global__ void k_layer1(const int* __restrict__ src, const int* __restrict__ dst,
                         const int* __restrict__ et, const float* __restrict__ W1) {
    int g = blockIdx.x * blockDim.x + threadIdx.x;
    int grp = g >> 3;        // which edge-quad
    int q = g & 7;           // which quarter of the 32-wide row
    if (grp >= Ee / 4) return;
    int e0 = grp * 4;

    int4 s4 = *(const int4*)(src + e0);
    int4 d4 = *(const int4*)(dst + e0);
    int4 r4 = *(const int4*)(et + e0);
    int ss[4] = {s4.x, s4.y, s4.z, s4.w};
    int dd[4] = {d4.x, d4.y, d4.z, d4.w};
    int rr[4] = {r4.x, r4.y, r4.z, r4.w};

    float  nn[4];
    float4 ww[4];
#pragma unroll
    for (int k = 0; k < 4; k++) {
        nn[k] = g_norm[rr[k] * Nn + dd[k]];
        ww[k] = *(const float4*)(W1 + (rr[k] * Nn + ss[k]) * Hh + q * 4);
    }
#pragma unroll
    for (int k = 0; k < 4; k++) {
        float4 v = make_float4(ww[k].x * nn[k], ww[k].y * nn[k],
                               ww[k].z * nn[k], ww[k].w * nn[k]);
        red_add_v4(&g_h1[dd[k] * Hh + q * 4], v);
    }
}

// ---------------------------------------------------------------------------
// h1 = relu(agg1 + root1 + b1)
// ---------------------------------------------------------------------------
__global__ void k_relu(const float* __restrict__ root1, const float* __restrict__ b1) {
    int i = blockIdx.x * blockDim.x + threadIdx.x;
    if (i < Nn * Hh) {
        float v = g_h1[i] + root1[i] + b1[i & (Hh - 1)];
        g_h1[i] = v > 0.0f ? v : 0.0f;
    }
}

// ---------------------------------------------------------------------------
// T[r,n,l] = sum_h h1[n,h] * W2[r,h,l].   Block = 256 threads = 32 nodes x 8 l.
// W2 (16KB) staged in shared; LDS reads are 8-consecutive-floats with 4-way
// broadcast -> conflict-free. Writes coalesce per r (4 nodes x 8 l = 128B).
// ---------------------------------------------------------------------------
__global__ void k_T(const float* __restrict__ W2) {
    __shared__ float sW[Rr * Hh * Ll];   // [r][h][l], 16KB
    for (int i = threadIdx.x; i < Rr * Hh * Ll; i += blockDim.x) sW[i] = W2[i];
    __syncthreads();

    int n = blockIdx.x * 32 + (threadIdx.x >> 3);
    int l = threadIdx.x & 7;
    if (n >= Nn) return;

    float acc[Rr];
#pragma unroll
    for (int r = 0; r < Rr; r++) acc[r] = 0.0f;

    const float4* hp = (const float4*)(g_h1 + n * Hh);
#pragma unroll
    for (int j = 0; j < 8; j++) {
        float4 hv = hp[j];
        float hs[4] = {hv.x, hv.y, hv.z, hv.w};
#pragma unroll
        for (int k = 0; k < 4; k++) {
            int h = j * 4 + k;
#pragma unroll
            for (int r = 0; r < Rr; r++)
                acc[r] += hs[k] * sW[(r * Hh + h) * Ll + l];
        }
    }
#pragma unroll
    for (int r = 0; r < Rr; r++) g_T[(r * Nn + n) * Ll + l] = acc[r];
}

// ---------------------------------------------------------------------------
// Layer 2 edge pass: 2 threads per edge (half-row each), 4 edges per thread.
//   out[dst, half*4..] += norm[r,dst] * T[r, src, half*4..]
// T is 25.6MB -> L2-resident gathers.
// ---------------------------------------------------------------------------
__global__ void k_layer2(const int* __restrict__ src, const int* __restrict__ dst,
                         const int* __restrict__ et, float* __restrict__ out) {
    int g = blockIdx.x * blockDim.x + threadIdx.x;
    int grp = g >> 1;
    int half = g & 1;
    if (grp >= Ee / 4) return;
    int e0 = grp * 4;

    int4 s4 = *(const int4*)(src + e0);
    int4 d4 = *(const int4*)(dst + e0);
    int4 r4 = *(const int4*)(et + e0);
    int ss[4] = {s4.x, s4.y, s4.z, s4.w};
    int dd[4] = {d4.x, d4.y, d4.z, d4.w};
    int rr[4] = {r4.x, r4.y, r4.z, r4.w};

    float  nn[4];
    float4 tv[4];
#pragma unroll
    for (int k = 0; k < 4; k++) {
        nn[k] = g_norm[rr[k] * Nn + dd[k]];
        tv[k] = *(const float4*)(g_T + (rr[k] * Nn + ss[k]) * Ll + half * 4);
    }
#pragma unroll
    for (int k = 0; k < 4; k++) {
        float4 v = make_float4(tv[k].x * nn[k], tv[k].y * nn[k],
                               tv[k].z * nn[k], tv[k].w * nn[k]);
        red_add_v4(&out[dd[k] * Ll + half * 4], v);
    }
}

// ---------------------------------------------------------------------------
// Final: out[n,l] = sigmoid(edge_acc[n,l] + (h1[n,:] @ root2)[l] + b2[l])
// ---------------------------------------------------------------------------
__global__ void k_final(const float* __restrict__ root2, const float* __restrict__ b2,
                        float* __restrict__ out) {
    __shared__ float sR[Hh * Ll];
    __shared__ float sB[Ll];
    for (int i = threadIdx.x; i < Hh * Ll; i += blockDim.x) sR[i] = root2[i];
    if (threadIdx.x < Ll) sB[threadIdx.x] = b2[threadIdx.x];
    __syncthreads();

    int n = blockIdx.x * blockDim.x + threadIdx.x;
    if (n >= Nn) return;

    float y[Ll];
#pragma unroll
    for (int l = 0; l < Ll; l++) y[l] = sB[l];

    const float4* hp = (const float4*)(g_h1 + n * Hh);
#pragma unroll
    for (int j = 0; j < 8; j++) {
        float4 hv = hp[j];
        float hvals[4] = {hv.x, hv.y, hv.z, hv.w};
#pragma unroll
        for (int k = 0; k < 4; k++) {
            int h = j * 4 + k;
#pragma unroll
            for (int l = 0; l < Ll; l++) y[l] += hvals[k] * sR[h * Ll + l];
        }
    }

#pragma unroll
    for (int l = 0; l < Ll; l++) {
        float v = out[n * Ll + l] + y[l];
        out[n * Ll + l] = 1.0f / (1.0f + expf(-v));
    }
}

// ---------------------------------------------------------------------------
extern "C" void kernel_launch(void* const* d_in, const int* in_sizes, int n_in,
                              void* d_out, int out_size) {
    const int* ei    = (const int*)d_in[0];    // edge_index [2, E]
    const int* et    = (const int*)d_in[1];    // edge_type  [E]
    const float* W1  = (const float*)d_in[2];  // [R, N, H]
    const float* rt1 = (const float*)d_in[3];  // [N, H]
    const float* b1  = (const float*)d_in[4];  // [H]
    const float* W2  = (const float*)d_in[5];  // [R, H, L]
    const float* rt2 = (const float*)d_in[6];  // [H, L]
    const float* b2  = (const float*)d_in[7];  // [L]
    float* out = (float*)d_out;                // [N, L]

    const int* src = ei;
    const int* dst = ei + Ee;

    k_zero<<<1024, 256>>>(out);
    k_count<<<(Ee / 4 + 255) / 256, 256>>>(et, dst);
    k_norm<<<(Rr * Nn + 255) / 256, 256>>>();
    k_layer1<<<(Ee / 4) * 8 / 256, 256>>>(src, dst, et, W1);   // 8 thr/edge, 4 edges/thr
    k_relu<<<(Nn * Hh + 255) / 256, 256>>>(rt1, b1);
    k_T<<<(Nn + 31) / 32, 256>>>(W2);
    k_layer2<<<(Ee / 4) * 2 / 256, 256>>>(src, dst, et, out);  // 2 thr/edge, 4 edges/thr
    k_final<<<(Nn + 255) / 256, 256>>>(rt2, b2, out);
}

// round 6
// speedup vs baseline: 5.1525x; 1.0280x over previous
#include <cuda_runtime.h>

#define Nn 50000
#define Rr 16
#define Hh 32
#define Ll 8
#define Ee 1600000

// Scratch (static __device__ arrays: allocation-free per harness rules)
__device__ __align__(16) int   g_cnt[Rr * Nn];       // per-(relation,dst) edge counts
__device__ __align__(16) float g_norm[Rr * Nn];      // 1/max(cnt,1)
__device__ __align__(16) float g_enorm[Ee];          // per-edge norm (written by layer1)
__device__ __align__(16) float g_h1[Nn * Hh];        // layer-1 hidden (agg -> relu'd)
__device__ __align__(16) float g_T[Rr * Nn * Ll];    // T[r,n,l] = (h1[n,:] @ W2[r])[l]

// Vector reduction: 4x fp32 add in one L2 atomic op (sm_90+)
__device__ __forceinline__ void red_add_v4(float* p, float4 v) {
    asm volatile("red.global.add.v4.f32 [%0], {%1,%2,%3,%4};"
                 :: "l"(p), "f"(v.x), "f"(v.y), "f"(v.z), "f"(v.w)
                 : "memory");
}

// Packed f32x2 FMA (sm_103a): acc = a * b + acc, two fp32 lanes per op
__device__ __forceinline__ void fma_f32x2(unsigned long long& acc,
                                          unsigned long long a,
                                          unsigned long long b) {
    asm("fma.rn.f32x2 %0, %1, %2, %0;" : "+l"(acc) : "l"(a), "l"(b));
}
__device__ __forceinline__ unsigned long long pack_f32x2(float lo, float hi) {
    unsigned long long r;
    asm("mov.b64 %0, {%1, %2};" : "=l"(r) : "f"(lo), "f"(hi));
    return r;
}
__device__ __forceinline__ void unpack_f32x2(unsigned long long v, float& lo, float& hi) {
    asm("mov.b64 {%0, %1}, %2;" : "=f"(lo), "=f"(hi) : "l"(v));
}

// ---------------------------------------------------------------------------
// Zero accumulators, vectorized (d_out is poisoned to 0xAA by the harness)
// ---------------------------------------------------------------------------
__global__ void k_zero(float* __restrict__ out) {
    int i = blockIdx.x * blockDim.x + threadIdx.x;
    int stride = gridDim.x * blockDim.x;
    float4 z = make_float4(0.f, 0.f, 0.f, 0.f);
    int4* c4 = (int4*)g_cnt;
    float4* h4 = (float4*)g_h1;
    float4* o4 = (float4*)out;
    for (int j = i; j < (Rr * Nn) / 4; j += stride) c4[j] = make_int4(0, 0, 0, 0);
    for (int j = i; j < (Nn * Hh) / 4; j += stride) h4[j] = z;
    for (int j = i; j < (Nn * Ll) / 4; j += stride) o4[j] = z;
}

// ---------------------------------------------------------------------------
// Per-(relation,dst) edge counts. 4 edges per thread via int4 index loads.
// ---------------------------------------------------------------------------
__global__ void k_count(const int* __restrict__ et, const int* __restrict__ dst) {
    int g = blockIdx.x * blockDim.x + threadIdx.x;
    if (g >= Ee / 4) return;
    int e0 = g * 4;
    int4 d4 = *(const int4*)(dst + e0);
    int4 r4 = *(const int4*)(et + e0);
    atomicAdd(&g_cnt[r4.x * Nn + d4.x], 1);
    atomicAdd(&g_cnt[r4.y * Nn + d4.y], 1);
    atomicAdd(&g_cnt[r4.z * Nn + d4.z], 1);
    atomicAdd(&g_cnt[r4.w * Nn + d4.w], 1);
}

// ---------------------------------------------------------------------------
// norm[r,d] = 1/max(cnt,1)
// ---------------------------------------------------------------------------
__global__ void k_norm() {
    int i = blockIdx.x * blockDim.x + threadIdx.x;
    if (i < Rr * Nn) g_norm[i] = 1.0f / fmaxf((float)g_cnt[i], 1.0f);
}

// ---------------------------------------------------------------------------
// Layer 1: 8 threads per edge (quarter-row each), 4 edges per thread.
//   g_h1[dst, q*4..q*4+3] += W1[r, src, q*4..] * norm[r,dst]
// Lane q==0 additionally stores the 4 edge-norms to g_enorm for layer2 reuse.
// ---------------------------------------------------------------------------
__global__ void k_layer1(const int* __restrict__ src, const int* __restrict__ dst,
                         const int* __restrict__ et, const float* __restrict__ W1) {
    int g = blockIdx.x * blockDim.x + threadIdx.x;
    int grp = g >> 3;        // which edge-quad
    int q = g & 7;           // which quarter of the 32-wide row
    if (grp >= Ee / 4) return;
    int e0 = grp * 4;

    int4 s4 = *(const int4*)(src + e0);
    int4 d4 = *(const int4*)(dst + e0);
    int4 r4 = *(const int4*)(et + e0);
    int ss[4] = {s4.x, s4.y, s4.z, s4.w};
    int dd[4] = {d4.x, d4.y, d4.z, d4.w};
    int rr[4] = {r4.x, r4.y, r4.z, r4.w};

    float  nn[4];
    float4 ww[4];
#pragma unroll
    for (int k = 0; k < 4; k++) {
        nn[k] = g_norm[rr[k] * Nn + dd[k]];
        ww[k] = *(const float4*)(W1 + (rr[k] * Nn + ss[k]) * Hh + q * 4);
    }
    if (q == 0) {
        *(float4*)(g_enorm + e0) = make_float4(nn[0], nn[1], nn[2], nn[3]);
    }
#pragma unroll
    for (int k = 0; k < 4; k++) {
        float4 v = make_float4(ww[k].x * nn[k], ww[k].y * nn[k],
                               ww[k].z * nn[k], ww[k].w * nn[k]);
        red_add_v4(&g_h1[dd[k] * Hh + q * 4], v);
    }
}

// ---------------------------------------------------------------------------
// Fused relu + T:  h1 = relu(agg1 + root1 + b1)  (stored back to g_h1),
//                  T[r,n,l] = sum_h h1[n,h] * W2[r,h,l]
// Block = 256 threads = 64 nodes x 4 l-pair threads. f32x2 packed FMAs:
// each thread computes l = 2*lp and 2*lp+1 together (adjacent in W2 memory).
// ---------------------------------------------------------------------------
__global__ void k_T(const float* __restrict__ W2, const float* __restrict__ root1,
                    const float* __restrict__ b1) {
    __shared__ float sW[Rr * Hh * Ll];   // [r][h][l], 16KB
    __shared__ float sB[Hh];
    for (int i = threadIdx.x; i < Rr * Hh * Ll; i += blockDim.x) sW[i] = W2[i];
    if (threadIdx.x < Hh) sB[threadIdx.x] = b1[threadIdx.x];
    __syncthreads();

    int n = blockIdx.x * 64 + (threadIdx.x >> 2);
    int lp = threadIdx.x & 3;            // l-pair index: l = 2*lp, 2*lp+1
    if (n >= Nn) return;

    // Load raw agg + root1, apply relu -> h[32]
    float h[Hh];
    const float4* ap = (const float4*)(g_h1 + n * Hh);
    const float4* rp = (const float4*)(root1 + n * Hh);
#pragma unroll
    for (int j = 0; j < 8; j++) {
        float4 av = ap[j];
        float4 rv = rp[j];
        h[j * 4 + 0] = fmaxf(av.x + rv.x + sB[j * 4 + 0], 0.0f);
        h[j * 4 + 1] = fmaxf(av.y + rv.y + sB[j * 4 + 1], 0.0f);
        h[j * 4 + 2] = fmaxf(av.z + rv.z + sB[j * 4 + 2], 0.0f);
        h[j * 4 + 3] = fmaxf(av.w + rv.w + sB[j * 4 + 3], 0.0f);
    }
    // One thread per node writes back relu'd h1 for k_final
    if (lp == 0) {
        float4* hw = (float4*)(g_h1 + n * Hh);
#pragma unroll
        for (int j = 0; j < 8; j++)
            hw[j] = make_float4(h[j * 4], h[j * 4 + 1], h[j * 4 + 2], h[j * 4 + 3]);
    }

    unsigned long long acc[Rr];
#pragma unroll
    for (int r = 0; r < Rr; r++) acc[r] = pack_f32x2(0.0f, 0.0f);

#pragma unroll
    for (int hh = 0; hh < Hh; hh++) {
        unsigned long long hv = pack_f32x2(h[hh], h[hh]);
#pragma unroll
        for (int r = 0; r < Rr; r++) {
            const float2* wp = (const float2*)(sW + (r * Hh + hh) * Ll + lp * 2);
            float2 w = *wp;
            fma_f32x2(acc[r], hv, pack_f32x2(w.x, w.y));
        }
    }
#pragma unroll
    for (int r = 0; r < Rr; r++) {
        float lo, hi;
        unpack_f32x2(acc[r], lo, hi);
        float2* tp = (float2*)(g_T + (r * Nn + n) * Ll + lp * 2);
        *tp = make_float2(lo, hi);
    }
}

// ---------------------------------------------------------------------------
// Layer 2 edge pass: 2 threads per edge (half-row each), 4 edges per thread.
//   out[dst, half*4..] += enorm[e] * T[r, src, half*4..]
// enorm is a coalesced/broadcast float4 load (no per-edge gather).
// ---------------------------------------------------------------------------
__global__ void k_layer2(const int* __restrict__ src, const int* __restrict__ dst,
                         const int* __restrict__ et, float* __restrict__ out) {
    int g = blockIdx.x * blockDim.x + threadIdx.x;
    int grp = g >> 1;
    int half = g & 1;
    if (grp >= Ee / 4) return;
    int e0 = grp * 4;

    int4 s4 = *(const int4*)(src + e0);
    int4 d4 = *(const int4*)(dst + e0);
    int4 r4 = *(const int4*)(et + e0);
    float4 n4 = *(const float4*)(g_enorm + e0);
    int ss[4] = {s4.x, s4.y, s4.z, s4.w};
    int dd[4] = {d4.x, d4.y, d4.z, d4.w};
    int rr[4] = {r4.x, r4.y, r4.z, r4.w};
    float nn[4] = {n4.x, n4.y, n4.z, n4.w};

    float4 tv[4];
#pragma unroll
    for (int k = 0; k < 4; k++) {
        tv[k] = *(const float4*)(g_T + (rr[k] * Nn + ss[k]) * Ll + half * 4);
    }
#pragma unroll
    for (int k = 0; k < 4; k++) {
        float4 v = make_float4(tv[k].x * nn[k], tv[k].y * nn[k],
                               tv[k].z * nn[k], tv[k].w * nn[k]);
        red_add_v4(&out[dd[k] * Ll + half * 4], v);
    }
}

// ---------------------------------------------------------------------------
// Final: out[n,l] = sigmoid(edge_acc[n,l] + (h1[n,:] @ root2)[l] + b2[l])
// ---------------------------------------------------------------------------
__global__ void k_final(const float* __restrict__ root2, const float* __restrict__ b2,
                        float* __restrict__ out) {
    __shared__ float sR[Hh * Ll];
    __shared__ float sB[Ll];
    for (int i = threadIdx.x; i < Hh * Ll; i += blockDim.x) sR[i] = root2[i];
    if (threadIdx.x < Ll) sB[threadIdx.x] = b2[threadIdx.x];
    __syncthreads();

    int n = blockIdx.x * blockDim.x + threadIdx.x;
    if (n >= Nn) return;

    float y[Ll];
#pragma unroll
    for (int l = 0; l < Ll; l++) y[l] = sB[l];

    const float4* hp = (const float4*)(g_h1 + n * Hh);
#pragma unroll
    for (int j = 0; j < 8; j++) {
        float4 hv = hp[j];
        float hvals[4] = {hv.x, hv.y, hv.z, hv.w};
#pragma unroll
        for (int k = 0; k < 4; k++) {
            int h = j * 4 + k;
#pragma unroll
            for (int l = 0; l < Ll; l++) y[l] += hvals[k] * sR[h * Ll + l];
        }
    }

#pragma unroll
    for (int l = 0; l < Ll; l++) {
        float v = out[n * Ll + l] + y[l];
        out[n * Ll + l] = 1.0f / (1.0f + expf(-v));
    }
}

// ---------------------------------------------------------------------------
extern "C" void kernel_launch(void* const* d_in, const int* in_sizes, int n_in,
                              void* d_out, int out_size) {
    const int* ei    = (const int*)d_in[0];    // edge_index [2, E]
    const int* et    = (const int*)d_in[1];    // edge_type  [E]
    const float* W1  = (const float*)d_in[2];  // [R, N, H]
    const float* rt1 = (const float*)d_in[3];  // [N, H]
    const float* b1  = (const float*)d_in[4];  // [H]
    const float* W2  = (const float*)d_in[5];  // [R, H, L]
    const float* rt2 = (const float*)d_in[6];  // [H, L]
    const float* b2  = (const float*)d_in[7];  // [L]
    float* out = (float*)d_out;                // [N, L]

    const int* src = ei;
    const int* dst = ei + Ee;

    k_zero<<<1024, 256>>>(out);
    k_count<<<(Ee / 4 + 255) / 256, 256>>>(et, dst);
    k_norm<<<(Rr * Nn + 255) / 256, 256>>>();
    k_layer1<<<(Ee / 4) * 8 / 256, 256>>>(src, dst, et, W1);   // 8 thr/edge, 4 edges/thr
    k_T<<<(Nn + 63) / 64, 256>>>(W2, rt1, b1);                 // fused relu + T, f32x2
    k_layer2<<<(Ee / 4) * 2 / 256, 256>>>(src, dst, et, out);  // 2 thr/edge, 4 edges/thr
    k_final<<<(Nn + 255) / 256, 256>>>(rt2, b2, out);
}

// round 7
// speedup vs baseline: 5.1551x; 1.0005x over previous
#include <cuda_runtime.h>

#define Nn 50000
#define Rr 16
#define Hh 32
#define Ll 8
#define Ee 1600000

// Scratch (static __device__ arrays: allocation-free per harness rules)
__device__ __align__(16) int   g_cnt[Rr * Nn];       // per-(relation,dst) edge counts
__device__ __align__(16) float g_norm[Rr * Nn];      // 1/max(cnt,1)
__device__ __align__(16) float g_enorm[Ee];          // per-edge norm (written by layer1)
__device__ __align__(16) float g_h1[Nn * Hh];        // layer-1 hidden (agg -> relu'd)
__device__ __align__(16) float g_T[Rr * Nn * Ll];    // T[r,n,l] = (h1[n,:] @ W2[r])[l]

// Vector reduction: 4x fp32 add in one L2 atomic op (sm_90+)
__device__ __forceinline__ void red_add_v4(float* p, float4 v) {
    asm volatile("red.global.add.v4.f32 [%0], {%1,%2,%3,%4};"
                 :: "l"(p), "f"(v.x), "f"(v.y), "f"(v.z), "f"(v.w)
                 : "memory");
}

// Packed f32x2 FMA (sm_103a): acc = a * b + acc, two fp32 lanes per op
__device__ __forceinline__ void fma_f32x2(unsigned long long& acc,
                                          unsigned long long a,
                                          unsigned long long b) {
    asm("fma.rn.f32x2 %0, %1, %2, %0;" : "+l"(acc) : "l"(a), "l"(b));
}
__device__ __forceinline__ unsigned long long pack_f32x2(float lo, float hi) {
    unsigned long long r;
    asm("mov.b64 %0, {%1, %2};" : "=l"(r) : "f"(lo), "f"(hi));
    return r;
}
__device__ __forceinline__ void unpack_f32x2(unsigned long long v, float& lo, float& hi) {
    asm("mov.b64 {%0, %1}, %2;" : "=f"(lo), "=f"(hi) : "l"(v));
}

// ---------------------------------------------------------------------------
// Zero accumulators, vectorized (d_out is poisoned to 0xAA by the harness)
// ---------------------------------------------------------------------------
__global__ void k_zero(float* __restrict__ out) {
    int i = blockIdx.x * blockDim.x + threadIdx.x;
    int stride = gridDim.x * blockDim.x;
    float4 z = make_float4(0.f, 0.f, 0.f, 0.f);
    int4* c4 = (int4*)g_cnt;
    float4* h4 = (float4*)g_h1;
    float4* o4 = (float4*)out;
    for (int j = i; j < (Rr * Nn) / 4; j += stride) c4[j] = make_int4(0, 0, 0, 0);
    for (int j = i; j < (Nn * Hh) / 4; j += stride) h4[j] = z;
    for (int j = i; j < (Nn * Ll) / 4; j += stride) o4[j] = z;
}

// ---------------------------------------------------------------------------
// Per-(relation,dst) edge counts. 4 edges per thread via int4 index loads.
// ---------------------------------------------------------------------------
__global__ void k_count(const int* __restrict__ et, const int* __restrict__ dst) {
    int g = blockIdx.x * blockDim.x + threadIdx.x;
    if (g >= Ee / 4) return;
    int e0 = g * 4;
    int4 d4 = *(const int4*)(dst + e0);
    int4 r4 = *(const int4*)(et + e0);
    atomicAdd(&g_cnt[r4.x * Nn + d4.x], 1);
    atomicAdd(&g_cnt[r4.y * Nn + d4.y], 1);
    atomicAdd(&g_cnt[r4.z * Nn + d4.z], 1);
    atomicAdd(&g_cnt[r4.w * Nn + d4.w], 1);
}

// ---------------------------------------------------------------------------
// norm[r,d] = 1/max(cnt,1)
// ---------------------------------------------------------------------------
__global__ void k_norm() {
    int i = blockIdx.x * blockDim.x + threadIdx.x;
    if (i < Rr * Nn) g_norm[i] = 1.0f / fmaxf((float)g_cnt[i], 1.0f);
}

// ---------------------------------------------------------------------------
// Layer 1: 8 threads per edge (quarter-row each), 4 edges per thread.
//   g_h1[dst, q*4..q*4+3] += W1[r, src, q*4..] * norm[r,dst]
// Lane q==0 additionally stores the 4 edge-norms to g_enorm for layer2 reuse.
// ---------------------------------------------------------------------------
__global__ void k_layer1(const int* __restrict__ src, const int* __restrict__ dst,
                         const int* __restrict__ et, const float* __restrict__ W1) {
    int g = blockIdx.x * blockDim.x + threadIdx.x;
    int grp = g >> 3;        // which edge-quad
    int q = g & 7;           // which quarter of the 32-wide row
    if (grp >= Ee / 4) return;
    int e0 = grp * 4;

    int4 s4 = *(const int4*)(src + e0);
    int4 d4 = *(const int4*)(dst + e0);
    int4 r4 = *(const int4*)(et + e0);
    int ss[4] = {s4.x, s4.y, s4.z, s4.w};
    int dd[4] = {d4.x, d4.y, d4.z, d4.w};
    int rr[4] = {r4.x, r4.y, r4.z, r4.w};

    float  nn[4];
    float4 ww[4];
#pragma unroll
    for (int k = 0; k < 4; k++) {
        nn[k] = g_norm[rr[k] * Nn + dd[k]];
        ww[k] = *(const float4*)(W1 + (rr[k] * Nn + ss[k]) * Hh + q * 4);
    }
    if (q == 0) {
        *(float4*)(g_enorm + e0) = make_float4(nn[0], nn[1], nn[2], nn[3]);
    }
#pragma unroll
    for (int k = 0; k < 4; k++) {
        float4 v = make_float4(ww[k].x * nn[k], ww[k].y * nn[k],
                               ww[k].z * nn[k], ww[k].w * nn[k]);
        red_add_v4(&g_h1[dd[k] * Hh + q * 4], v);
    }
}

// ---------------------------------------------------------------------------
// Fused relu + T:  h1 = relu(agg1 + root1 + b1)  (stored back to g_h1),
//                  T[r,n,l] = sum_h h1[n,h] * W2[r,h,l]
// Block = 256 threads = 64 nodes x 4 l-pair threads. f32x2 packed FMAs:
// each thread computes l = 2*lp and 2*lp+1 together (adjacent in W2 memory).
// ---------------------------------------------------------------------------
__global__ void k_T(const float* __restrict__ W2, const float* __restrict__ root1,
                    const float* __restrict__ b1) {
    __shared__ float sW[Rr * Hh * Ll];   // [r][h][l], 16KB
    __shared__ float sB[Hh];
    for (int i = threadIdx.x; i < Rr * Hh * Ll; i += blockDim.x) sW[i] = W2[i];
    if (threadIdx.x < Hh) sB[threadIdx.x] = b1[threadIdx.x];
    __syncthreads();

    int n = blockIdx.x * 64 + (threadIdx.x >> 2);
    int lp = threadIdx.x & 3;            // l-pair index: l = 2*lp, 2*lp+1
    if (n >= Nn) return;

    // Load raw agg + root1, apply relu -> h[32]
    float h[Hh];
    const float4* ap = (const float4*)(g_h1 + n * Hh);
    const float4* rp = (const float4*)(root1 + n * Hh);
#pragma unroll
    for (int j = 0; j < 8; j++) {
        float4 av = ap[j];
        float4 rv = rp[j];
        h[j * 4 + 0] = fmaxf(av.x + rv.x + sB[j * 4 + 0], 0.0f);
        h[j * 4 + 1] = fmaxf(av.y + rv.y + sB[j * 4 + 1], 0.0f);
        h[j * 4 + 2] = fmaxf(av.z + rv.z + sB[j * 4 + 2], 0.0f);
        h[j * 4 + 3] = fmaxf(av.w + rv.w + sB[j * 4 + 3], 0.0f);
    }
    // One thread per node writes back relu'd h1 for k_final
    if (lp == 0) {
        float4* hw = (float4*)(g_h1 + n * Hh);
#pragma unroll
        for (int j = 0; j < 8; j++)
            hw[j] = make_float4(h[j * 4], h[j * 4 + 1], h[j * 4 + 2], h[j * 4 + 3]);
    }

    unsigned long long acc[Rr];
#pragma unroll
    for (int r = 0; r < Rr; r++) acc[r] = pack_f32x2(0.0f, 0.0f);

#pragma unroll
    for (int hh = 0; hh < Hh; hh++) {
        unsigned long long hv = pack_f32x2(h[hh], h[hh]);
#pragma unroll
        for (int r = 0; r < Rr; r++) {
            const float2* wp = (const float2*)(sW + (r * Hh + hh) * Ll + lp * 2);
            float2 w = *wp;
            fma_f32x2(acc[r], hv, pack_f32x2(w.x, w.y));
        }
    }
#pragma unroll
    for (int r = 0; r < Rr; r++) {
        float lo, hi;
        unpack_f32x2(acc[r], lo, hi);
        float2* tp = (float2*)(g_T + (r * Nn + n) * Ll + lp * 2);
        *tp = make_float2(lo, hi);
    }
}

// ---------------------------------------------------------------------------
// Layer 2 edge pass: 2 threads per edge (half-row each), 4 edges per thread.
//   out[dst, half*4..] += enorm[e] * T[r, src, half*4..]
// enorm is a coalesced/broadcast float4 load (no per-edge gather).
// ---------------------------------------------------------------------------
__global__ void k_layer2(const int* __restrict__ src, const int* __restrict__ dst,
                         const int* __restrict__ et, float* __restrict__ out) {
    int g = blockIdx.x * blockDim.x + threadIdx.x;
    int grp = g >> 1;
    int half = g & 1;
    if (grp >= Ee / 4) return;
    int e0 = grp * 4;

    int4 s4 = *(const int4*)(src + e0);
    int4 d4 = *(const int4*)(dst + e0);
    int4 r4 = *(const int4*)(et + e0);
    float4 n4 = *(const float4*)(g_enorm + e0);
    int ss[4] = {s4.x, s4.y, s4.z, s4.w};
    int dd[4] = {d4.x, d4.y, d4.z, d4.w};
    int rr[4] = {r4.x, r4.y, r4.z, r4.w};
    float nn[4] = {n4.x, n4.y, n4.z, n4.w};

    float4 tv[4];
#pragma unroll
    for (int k = 0; k < 4; k++) {
        tv[k] = *(const float4*)(g_T + (rr[k] * Nn + ss[k]) * Ll + half * 4);
    }
#pragma unroll
    for (int k = 0; k < 4; k++) {
        float4 v = make_float4(tv[k].x * nn[k], tv[k].y * nn[k],
                               tv[k].z * nn[k], tv[k].w * nn[k]);
        red_add_v4(&out[dd[k] * Ll + half * 4], v);
    }
}

// ---------------------------------------------------------------------------
// Final: out[n,l] = sigmoid(edge_acc[n,l] + (h1[n,:] @ root2)[l] + b2[l])
// ---------------------------------------------------------------------------
__global__ void k_final(const float* __restrict__ root2, const float* __restrict__ b2,
                        float* __restrict__ out) {
    __shared__ float sR[Hh * Ll];
    __shared__ float sB[Ll];
    for (int i = threadIdx.x; i < Hh * Ll; i += blockDim.x) sR[i] = root2[i];
    if (threadIdx.x < Ll) sB[threadIdx.x] = b2[threadIdx.x];
    __syncthreads();

    int n = blockIdx.x * blockDim.x + threadIdx.x;
    if (n >= Nn) return;

    float y[Ll];
#pragma unroll
    for (int l = 0; l < Ll; l++) y[l] = sB[l];

    const float4* hp = (const float4*)(g_h1 + n * Hh);
#pragma unroll
    for (int j = 0; j < 8; j++) {
        float4 hv = hp[j];
        float hvals[4] = {hv.x, hv.y, hv.z, hv.w};
#pragma unroll
        for (int k = 0; k < 4; k++) {
            int h = j * 4 + k;
#pragma unroll
            for (int l = 0; l < Ll; l++) y[l] += hvals[k] * sR[h * Ll + l];
        }
    }

#pragma unroll
    for (int l = 0; l < Ll; l++) {
        float v = out[n * Ll + l] + y[l];
        out[n * Ll + l] = 1.0f / (1.0f + expf(-v));
    }
}

// ---------------------------------------------------------------------------
extern "C" void kernel_launch(void* const* d_in, const int* in_sizes, int n_in,
                              void* d_out, int out_size) {
    const int* ei    = (const int*)d_in[0];    // edge_index [2, E]
    const int* et    = (const int*)d_in[1];    // edge_type  [E]
    const float* W1  = (const float*)d_in[2];  // [R, N, H]
    const float* rt1 = (const float*)d_in[3];  // [N, H]
    const float* b1  = (const float*)d_in[4];  // [H]
    const float* W2  = (const float*)d_in[5];  // [R, H, L]
    const float* rt2 = (const float*)d_in[6];  // [H, L]
    const float* b2  = (const float*)d_in[7];  // [L]
    float* out = (float*)d_out;                // [N, L]

    const int* src = ei;
    const int* dst = ei + Ee;

    k_zero<<<1024, 256>>>(out);
    k_count<<<(Ee / 4 + 255) / 256, 256>>>(et, dst);
    k_norm<<<(Rr * Nn + 255) / 256, 256>>>();
    k_layer1<<<(Ee / 4) * 8 / 256, 256>>>(src, dst, et, W1);   // 8 thr/edge, 4 edges/thr
    k_T<<<(Nn + 63) / 64, 256>>>(W2, rt1, b1);                 // fused relu + T, f32x2
    k_layer2<<<(Ee / 4) * 2 / 256, 256>>>(src, dst, et, out);  // 2 thr/edge, 4 edges/thr
    k_final<<<(Nn + 255) / 256, 256>>>(rt2, b2, out);
}